// round 5
// baseline (speedup 1.0000x reference)
#include <cuda_runtime.h>
#include <math.h>
#include <stdint.h>

// Shapes (fixed by the problem)
#define BB   4
#define NN   2048
#define DD   1024
#define DLL  64
#define DKK  128
#define DCC  8

// -------- device scratch (static: no allocations allowed) --------
__device__ float g_lam[BB];
__device__ float g_u[BB*9*DD];       // u_0 = W_K^T (q/tau); u_r = W_K^T qB_r
__device__ float g_score[BB*NN];
__device__ float g_screen[BB*NN];
__device__ float g_y[BB*DD];         // y[b] = sum_n attn[b,n] * x_keys[b,n,:]

// ================= K1: prep — q, qB, U (one block per batch) =================
__global__ void __launch_bounds__(256) k_prep(
    const float* __restrict__ xq, const float* __restrict__ zq,
    const float* __restrict__ WQ, const float* __restrict__ WQz,
    const float* __restrict__ WQg, const float* __restrict__ WK,
    const float* __restrict__ bb, const float* __restrict__ be,
    const float* __restrict__ bo) {
    int b = blockIdx.x, t = threadIdx.x, warp = t >> 5, lane = t & 31;
    __shared__ float zs[DLL];
    __shared__ float qs[DKK];
    __shared__ float qBs[DCC*DKK];
    __shared__ float s_tauinv;
    if (t < DLL) zs[t] = zq[b*DLL + t];
    __syncthreads();
    if (t == 0) {
        float r = 0.f;
        for (int l = 0; l < DLL; l++) r += zs[l]*zs[l];
        r = fminf(r, 1.f - 1e-6f);
        float lam = 2.f/(1.f - r + 1e-6f);
        g_lam[b] = lam;
        s_tauinv = lam / sqrtf((float)DKK);   // q_scaled = q * lam/sqrt(dk)
    }
    __syncthreads();
    const float tinv = s_tauinv;

    // q[a] (scaled by 1/tau): warp computes 16 a's
    const float* x = xq + b*DD;
    for (int i = 0; i < 16; i++) {
        int a = warp*16 + i;
        const float* wq = WQ + a*DD;
        float s = 0.f;
        for (int d = lane; d < DD; d += 32) s += x[d]*wq[d];
        for (int l = lane; l < DLL; l += 32) s += zs[l]*WQz[a*DLL + l];
        const float* G = WQg + a*DLL*DLL;
        for (int idx = lane; idx < DLL*DLL; idx += 32)
            s += G[idx]*zs[idx >> 6]*zs[idx & 63];
        #pragma unroll
        for (int o = 16; o; o >>= 1) s += __shfl_xor_sync(0xffffffffu, s, o);
        if (lane == 0) qs[a] = s * tinv;
    }
    __syncthreads();

    // qB[r][j] = sum_i qs[i] * skew-basis[r][i][j]
    #pragma unroll
    for (int ii = 0; ii < 4; ii++) {
        int idx = t + ii*256;                // 0..1023
        int r = idx >> 7, j = idx & 127;
        int rb = r << 14;
        float acc = 0.f;
        #pragma unroll 4
        for (int i = 0; i < DKK; i++) {
            int ij = rb | (i << 7) | j;
            int ji = rb | (j << 7) | i;
            float bs = (bb[ij]-bb[ji]) + 0.5f*(be[ij]-be[ji]) + 0.3f*(bo[ij]-bo[ji]);
            acc += qs[i]*bs;
        }
        qBs[idx] = acc;
    }
    __syncthreads();

    // U[r][d] = sum_a e_r[a] * WK[a][d],  e_0 = qs, e_r = qBs[r-1]
    float acc[4][9];
    #pragma unroll
    for (int i = 0; i < 4; i++)
        #pragma unroll
        for (int r = 0; r < 9; r++) acc[i][r] = 0.f;
    for (int a = 0; a < DKK; a++) {
        float e[9];
        e[0] = qs[a];
        #pragma unroll
        for (int r = 0; r < 8; r++) e[r+1] = qBs[r*DKK + a];
        const float* wk = WK + (size_t)a*DD;
        #pragma unroll
        for (int i = 0; i < 4; i++) {
            float w = wk[t + i*256];
            #pragma unroll
            for (int r = 0; r < 9; r++) acc[i][r] += e[r]*w;
        }
    }
    float* ub = g_u + b*9*DD;
    #pragma unroll
    for (int i = 0; i < 4; i++)
        #pragma unroll
        for (int r = 0; r < 9; r++) ub[r*DD + t + i*256] = acc[i][r];
}

// ================= K2: scores + screening =================
// grid (32 ntiles, 4 b), 256 threads; block handles 64 rows.
__global__ void __launch_bounds__(256) k_score(
    const float* __restrict__ xk, const float* __restrict__ zq,
    const float* __restrict__ zk, const float* __restrict__ Wd,
    const float* __restrict__ logsig) {
    int b = blockIdx.y;
    int n0 = blockIdx.x * 64;
    int t = threadIdx.x, warp = t >> 5, lane = t & 31;
    __shared__ float su[9*DD];           // 36 KB
    __shared__ float scoef[64][DCC];
    __shared__ float sdist[64];
    __shared__ float szq[DLL];

    for (int idx = t; idx < 9*DD; idx += 256) su[idx] = g_u[b*9*DD + idx];
    if (t < DLL) szq[t] = zq[b*DLL + t];
    __syncthreads();

    // coeff + dist: warp handles 8 rows
    for (int rr = 0; rr < 8; rr++) {
        int row = warp*8 + rr;
        int n = n0 + row;
        const float* zkp = zk + ((size_t)b*NN + n)*DLL;
        float d0 = szq[lane] - zkp[lane];
        float d1 = szq[lane+32] - zkp[lane+32];
        float dist = d0*d0 + d1*d1;
        #pragma unroll
        for (int o = 16; o; o >>= 1) dist += __shfl_xor_sync(0xffffffffu, dist, o);
        if (lane == 0) sdist[row] = dist;
        #pragma unroll
        for (int r = 0; r < DCC; r++) {
            float p = d0*Wd[r*DLL + lane] + d1*Wd[r*DLL + 32 + lane];
            #pragma unroll
            for (int o = 16; o; o >>= 1) p += __shfl_xor_sync(0xffffffffu, p, o);
            if (lane == 0) scoef[row][r] = p;
        }
    }
    __syncthreads();

    float lam = g_lam[b];
    float sfac = -expf(logsig[0]) * 0.5f * lam * lam;

    // 9-dot products: warp handles 8 rows, groups of 4
    for (int g = 0; g < 2; g++) {
        int row = warp*8 + g*4;
        int n = n0 + row;
        float acc[4][9];
        #pragma unroll
        for (int i = 0; i < 4; i++)
            #pragma unroll
            for (int r = 0; r < 9; r++) acc[i][r] = 0.f;
        const float* xp = xk + ((size_t)b*NN + n)*DD;
        for (int ds = 0; ds < 32; ds++) {
            int d = ds*32 + lane;
            float uu[9];
            #pragma unroll
            for (int r = 0; r < 9; r++) uu[r] = su[r*DD + d];
            #pragma unroll
            for (int i = 0; i < 4; i++) {
                float xv = xp[(size_t)i*DD + d];
                #pragma unroll
                for (int r = 0; r < 9; r++) acc[i][r] += uu[r]*xv;
            }
        }
        #pragma unroll
        for (int i = 0; i < 4; i++) {
            #pragma unroll
            for (int r = 0; r < 9; r++) {
                #pragma unroll
                for (int o = 16; o; o >>= 1)
                    acc[i][r] += __shfl_xor_sync(0xffffffffu, acc[i][r], o);
            }
            if (lane == 0) {
                float s = acc[i][0];
                #pragma unroll
                for (int r = 0; r < 8; r++) s += scoef[row+i][r] * acc[i][r+1];
                g_score[b*NN + n + i] = s;
                g_screen[b*NN + n + i] = expf(sfac * sdist[row+i]);
            }
        }
    }
}

// ================= K3: softmax stats (in-block) + y = sum_n w_n x_bn =================
// grid (32 dtiles, 4 b), 256 threads = 32 d x 8 n-strips.
__global__ void __launch_bounds__(256) k_y(const float* __restrict__ xk) {
    int b = blockIdx.y;
    int t = threadIdx.x;
    __shared__ float w[NN];              // 8 KB
    __shared__ float red[256];
    const float* sc = g_score + b*NN;

    float m = -1e30f;
    for (int i = t; i < NN; i += 256) m = fmaxf(m, sc[i]);
    red[t] = m; __syncthreads();
    for (int o = 128; o; o >>= 1) { if (t < o) red[t] = fmaxf(red[t], red[t+o]); __syncthreads(); }
    m = red[0]; __syncthreads();
    float z = 0.f;
    for (int i = t; i < NN; i += 256) z += expf(sc[i] - m);
    red[t] = z; __syncthreads();
    for (int o = 128; o; o >>= 1) { if (t < o) red[t] += red[t+o]; __syncthreads(); }
    float Z = red[0]; __syncthreads();

    for (int i = t; i < NN; i += 256)
        w[i] = expf(sc[i] - m) / Z * g_screen[b*NN + i];
    __syncthreads();

    int dl = t & 31, strip = t >> 5;
    int d = blockIdx.x*32 + dl;
    float acc = 0.f;
    const float* xp = xk + (size_t)b*NN*DD + d;
    for (int n = strip; n < NN; n += 8) acc += w[n] * xp[(size_t)n*DD];
    red[t] = acc; __syncthreads();
    if (strip == 0) {
        float s = 0.f;
        #pragma unroll
        for (int k = 0; k < 8; k++) s += red[dl + k*32];
        g_y[b*DD + d] = s;
    }
}

// ================= K4: av = W_V y; out = W_O av =================
__global__ void __launch_bounds__(256) k_out(const float* __restrict__ WV,
                                             const float* __restrict__ WO,
                                             float* __restrict__ out) {
    int b = blockIdx.x;
    int t = threadIdx.x, warp = t >> 5, lane = t & 31;
    __shared__ float sy[DD];
    __shared__ float sav[DKK];
    #pragma unroll
    for (int i = 0; i < 4; i++) sy[t + i*256] = g_y[b*DD + t + i*256];
    __syncthreads();
    // av[a] = sum_d sy[d] * WV[a][d]: warp computes 16 a's
    for (int i = 0; i < 16; i++) {
        int a = warp*16 + i;
        const float* wv = WV + (size_t)a*DD;
        float s = 0.f;
        for (int d = lane; d < DD; d += 32) s += sy[d]*wv[d];
        #pragma unroll
        for (int o = 16; o; o >>= 1) s += __shfl_xor_sync(0xffffffffu, s, o);
        if (lane == 0) sav[a] = s;
    }
    __syncthreads();
    #pragma unroll
    for (int ii = 0; ii < 4; ii++) {
        int d = t + ii*256;
        const float4* wo = (const float4*)(WO + (size_t)d*DKK);
        float s = 0.f;
        #pragma unroll 8
        for (int a4 = 0; a4 < 32; a4++) {
            float4 wvv = wo[a4];
            s += sav[a4*4+0]*wvv.x + sav[a4*4+1]*wvv.y
               + sav[a4*4+2]*wvv.z + sav[a4*4+3]*wvv.w;
        }
        out[b*DD + d] = s;
    }
}

extern "C" void kernel_launch(void* const* d_in, const int* in_sizes, int n_in,
                              void* d_out, int out_size) {
    const float* x_query   = (const float*)d_in[0];
    const float* z_query   = (const float*)d_in[1];
    const float* x_keys    = (const float*)d_in[2];
    const float* z_keys    = (const float*)d_in[3];
    const float* W_Q       = (const float*)d_in[4];
    const float* W_Qz      = (const float*)d_in[5];
    const float* W_Qg      = (const float*)d_in[6];
    const float* W_K       = (const float*)d_in[7];
    const float* W_V       = (const float*)d_in[8];
    const float* W_O       = (const float*)d_in[9];
    const float* W_delta   = (const float*)d_in[10];
    const float* basis_b   = (const float*)d_in[11];
    const float* basis_e   = (const float*)d_in[12];
    const float* basis_o   = (const float*)d_in[13];
    const float* log_sigma = (const float*)d_in[14];
    float* out = (float*)d_out;

    k_prep<<<BB, 256>>>(x_query, z_query, W_Q, W_Qz, W_Qg, W_K,
                        basis_b, basis_e, basis_o);
    k_score<<<dim3(32, BB), 256>>>(x_keys, z_query, z_keys, W_delta, log_sigma);
    k_y<<<dim3(32, BB), 256>>>(x_keys);
    k_out<<<BB, 256>>>(W_V, W_O, out);
}

// round 6
// speedup vs baseline: 5.5378x; 5.5378x over previous
#include <cuda_runtime.h>
#include <math.h>
#include <stdint.h>

// Shapes (fixed by the problem)
#define BB   4
#define NN   2048
#define DD   1024
#define DLL  64
#define DKK  128
#define DCC  8

// -------- device scratch (static: no allocations allowed) --------
__device__ float g_lam[BB];
__device__ float g_q[BB*DKK];        // q / tau
__device__ float g_qB[BB*DCC*DKK];   // (q/tau)^T basis_r
__device__ float g_u[BB*9*DD];       // u_0 = W_K^T (q/tau); u_r = W_K^T qB_r
__device__ float g_score[BB*NN];
__device__ float g_screen[BB*NN];
__device__ float g_y[BB*DD];         // y[b] = sum_n attn[b,n] * x_keys[b,n,:]
__device__ float g_av[BB*DKK];       // av = W_V y

// ======== K1: q[b,a] (scaled by 1/tau) — grid (128 a, 4 b), 128 thr ========
__global__ void __launch_bounds__(128) k_q(
    const float* __restrict__ xq, const float* __restrict__ zq,
    const float* __restrict__ WQ, const float* __restrict__ WQz,
    const float* __restrict__ WQg) {
    int a = blockIdx.x, b = blockIdx.y;
    int t = threadIdx.x;
    __shared__ float zs[DLL];
    __shared__ float red[128];
    if (t < DLL) zs[t] = zq[b*DLL + t];
    __syncthreads();
    float s = 0.f;
    const float* wq = WQ + a*DD;
    const float* x  = xq + b*DD;
    for (int d = t; d < DD; d += 128) s += x[d]*wq[d];
    if (t < DLL) s += zs[t]*WQz[a*DLL + t];
    const float* G = WQg + a*DLL*DLL;
    for (int idx = t; idx < DLL*DLL; idx += 128)
        s += G[idx]*zs[idx >> 6]*zs[idx & 63];
    red[t] = s; __syncthreads();
    for (int off = 64; off > 0; off >>= 1) {
        if (t < off) red[t] += red[t+off];
        __syncthreads();
    }
    if (t == 0) {
        float rsq = 0.f;
        for (int l = 0; l < DLL; l++) rsq += zs[l]*zs[l];
        rsq = fminf(rsq, 1.f - 1e-6f);
        float lam = 2.f/(1.f - rsq + 1e-6f);
        g_q[b*DKK + a] = red[0] * lam / sqrtf((float)DKK);
        if (a == 0) g_lam[b] = lam;
    }
}

// ======== K2: qB[b,r,j] = sum_i q_i * skew-basis — grid (8 r, 4 b), 128 thr ========
__global__ void __launch_bounds__(128) k_qB(
    const float* __restrict__ bb, const float* __restrict__ be,
    const float* __restrict__ bo) {
    int r = blockIdx.x, b = blockIdx.y;
    int j = threadIdx.x;
    const float* qb = g_q + b*DKK;
    int rb = r << 14;
    float acc = 0.f;
    #pragma unroll 4
    for (int i = 0; i < DKK; i++) {
        int ij = rb | (i << 7) | j;
        int ji = rb | (j << 7) | i;
        float bs = (bb[ij]-bb[ji]) + 0.5f*(be[ij]-be[ji]) + 0.3f*(bo[ij]-bo[ji]);
        acc += qb[i]*bs;
    }
    g_qB[(b*DCC + r)*DKK + j] = acc;
}

// ======== K3: U[b,r,d] = sum_a e_r[a]*WK[a,d] — grid (8 dtiles, 4 b), 128 thr ========
__global__ void __launch_bounds__(128) k_u(const float* __restrict__ WK) {
    int b = blockIdx.y, t = threadIdx.x;
    int d = blockIdx.x*128 + t;
    __shared__ float e[9*DKK];
    for (int idx = t; idx < 9*DKK; idx += 128)
        e[idx] = (idx < DKK) ? g_q[b*DKK + idx] : g_qB[b*DCC*DKK + idx - DKK];
    __syncthreads();
    float acc[9];
    #pragma unroll
    for (int r = 0; r < 9; r++) acc[r] = 0.f;
    #pragma unroll 4
    for (int a = 0; a < DKK; a++) {
        float w = WK[(size_t)a*DD + d];
        #pragma unroll
        for (int r = 0; r < 9; r++) acc[r] += e[r*DKK + a]*w;
    }
    #pragma unroll
    for (int r = 0; r < 9; r++) g_u[b*9*DD + r*DD + d] = acc[r];
}

// ======== K4: scores + screening — grid (32 ntiles, 4 b), 256 thr ========
__global__ void __launch_bounds__(256) k_score(
    const float* __restrict__ xk, const float* __restrict__ zq,
    const float* __restrict__ zk, const float* __restrict__ Wd,
    const float* __restrict__ logsig) {
    int b = blockIdx.y;
    int n0 = blockIdx.x * 64;
    int t = threadIdx.x, warp = t >> 5, lane = t & 31;
    __shared__ float su[9*DD];           // 36 KB
    __shared__ float scoef[64][DCC];
    __shared__ float sdist[64];
    __shared__ float szq[DLL];

    for (int idx = t; idx < 9*DD; idx += 256) su[idx] = g_u[b*9*DD + idx];
    if (t < DLL) szq[t] = zq[b*DLL + t];
    __syncthreads();

    // coeff + dist: warp handles 8 rows
    for (int rr = 0; rr < 8; rr++) {
        int row = warp*8 + rr;
        int n = n0 + row;
        const float* zkp = zk + ((size_t)b*NN + n)*DLL;
        float d0 = szq[lane] - zkp[lane];
        float d1 = szq[lane+32] - zkp[lane+32];
        float dist = d0*d0 + d1*d1;
        #pragma unroll
        for (int o = 16; o; o >>= 1) dist += __shfl_xor_sync(0xffffffffu, dist, o);
        if (lane == 0) sdist[row] = dist;
        #pragma unroll
        for (int r = 0; r < DCC; r++) {
            float p = d0*Wd[r*DLL + lane] + d1*Wd[r*DLL + 32 + lane];
            #pragma unroll
            for (int o = 16; o; o >>= 1) p += __shfl_xor_sync(0xffffffffu, p, o);
            if (lane == 0) scoef[row][r] = p;
        }
    }
    __syncthreads();

    float lam = g_lam[b];
    float sfac = -expf(logsig[0]) * 0.5f * lam * lam;

    // 9-dot products: warp handles 8 rows, groups of 4
    for (int g = 0; g < 2; g++) {
        int row = warp*8 + g*4;
        int n = n0 + row;
        float acc[4][9];
        #pragma unroll
        for (int i = 0; i < 4; i++)
            #pragma unroll
            for (int r = 0; r < 9; r++) acc[i][r] = 0.f;
        const float* xp = xk + ((size_t)b*NN + n)*DD;
        for (int ds = 0; ds < 32; ds++) {
            int d = ds*32 + lane;
            float uu[9];
            #pragma unroll
            for (int r = 0; r < 9; r++) uu[r] = su[r*DD + d];
            #pragma unroll
            for (int i = 0; i < 4; i++) {
                float xv = xp[(size_t)i*DD + d];
                #pragma unroll
                for (int r = 0; r < 9; r++) acc[i][r] += uu[r]*xv;
            }
        }
        #pragma unroll
        for (int i = 0; i < 4; i++) {
            #pragma unroll
            for (int r = 0; r < 9; r++) {
                #pragma unroll
                for (int o = 16; o; o >>= 1)
                    acc[i][r] += __shfl_xor_sync(0xffffffffu, acc[i][r], o);
            }
            if (lane == 0) {
                float s = acc[i][0];
                #pragma unroll
                for (int r = 0; r < 8; r++) s += scoef[row+i][r] * acc[i][r+1];
                g_score[b*NN + n + i] = s;
                g_screen[b*NN + n + i] = expf(sfac * sdist[row+i]);
            }
        }
    }
}

// ======== K5: softmax stats (in-block) + y = sum_n w_n x_bn — grid (32, 4) ========
__global__ void __launch_bounds__(256) k_y(const float* __restrict__ xk) {
    int b = blockIdx.y;
    int t = threadIdx.x;
    __shared__ float w[NN];              // 8 KB
    __shared__ float red[256];
    const float* sc = g_score + b*NN;

    float m = -1e30f;
    for (int i = t; i < NN; i += 256) m = fmaxf(m, sc[i]);
    red[t] = m; __syncthreads();
    for (int o = 128; o; o >>= 1) { if (t < o) red[t] = fmaxf(red[t], red[t+o]); __syncthreads(); }
    m = red[0]; __syncthreads();
    float z = 0.f;
    for (int i = t; i < NN; i += 256) z += expf(sc[i] - m);
    red[t] = z; __syncthreads();
    for (int o = 128; o; o >>= 1) { if (t < o) red[t] += red[t+o]; __syncthreads(); }
    float Z = red[0]; __syncthreads();

    for (int i = t; i < NN; i += 256)
        w[i] = expf(sc[i] - m) / Z * g_screen[b*NN + i];
    __syncthreads();

    int dl = t & 31, strip = t >> 5;
    int d = blockIdx.x*32 + dl;
    float acc = 0.f;
    const float* xp = xk + (size_t)b*NN*DD + d;
    #pragma unroll 4
    for (int n = strip; n < NN; n += 8) acc += w[n] * xp[(size_t)n*DD];
    red[t] = acc; __syncthreads();
    if (strip == 0) {
        float s = 0.f;
        #pragma unroll
        for (int k = 0; k < 8; k++) s += red[dl + k*32];
        g_y[b*DD + d] = s;
    }
}

// ======== K6: av[b,a] = sum_d y[d]*WV[a,d] — grid (128 a, 4 b), 128 thr ========
__global__ void __launch_bounds__(128) k_av(const float* __restrict__ WV) {
    int a = blockIdx.x, b = blockIdx.y;
    int t = threadIdx.x;
    __shared__ float red[128];
    const float* wv = WV + (size_t)a*DD;
    const float* y = g_y + b*DD;
    float s = 0.f;
    #pragma unroll
    for (int i = 0; i < 8; i++) s += y[t + i*128]*wv[t + i*128];
    red[t] = s; __syncthreads();
    for (int o = 64; o; o >>= 1) { if (t < o) red[t] += red[t+o]; __syncthreads(); }
    if (t == 0) g_av[b*DKK + a] = red[0];
}

// ======== K7: out[b,d] = sum_a av[a]*WO[d,a] — grid (4 dtiles, 4 b), 256 thr ========
__global__ void __launch_bounds__(256) k_o(const float* __restrict__ WO,
                                           float* __restrict__ out) {
    int b = blockIdx.y;
    int t = threadIdx.x;
    int d = blockIdx.x*256 + t;
    __shared__ float av[DKK];
    if (t < DKK) av[t] = g_av[b*DKK + t];
    __syncthreads();
    float s = 0.f;
    const float4* wo = (const float4*)(WO + (size_t)d*DKK);
    #pragma unroll 8
    for (int a4 = 0; a4 < 32; a4++) {
        float4 wv = wo[a4];
        s += av[a4*4+0]*wv.x + av[a4*4+1]*wv.y + av[a4*4+2]*wv.z + av[a4*4+3]*wv.w;
    }
    out[b*DD + d] = s;
}

extern "C" void kernel_launch(void* const* d_in, const int* in_sizes, int n_in,
                              void* d_out, int out_size) {
    const float* x_query   = (const float*)d_in[0];
    const float* z_query   = (const float*)d_in[1];
    const float* x_keys    = (const float*)d_in[2];
    const float* z_keys    = (const float*)d_in[3];
    const float* W_Q       = (const float*)d_in[4];
    const float* W_Qz      = (const float*)d_in[5];
    const float* W_Qg      = (const float*)d_in[6];
    const float* W_K       = (const float*)d_in[7];
    const float* W_V       = (const float*)d_in[8];
    const float* W_O       = (const float*)d_in[9];
    const float* W_delta   = (const float*)d_in[10];
    const float* basis_b   = (const float*)d_in[11];
    const float* basis_e   = (const float*)d_in[12];
    const float* basis_o   = (const float*)d_in[13];
    const float* log_sigma = (const float*)d_in[14];
    float* out = (float*)d_out;

    k_q<<<dim3(DKK, BB), 128>>>(x_query, z_query, W_Q, W_Qz, W_Qg);
    k_qB<<<dim3(DCC, BB), 128>>>(basis_b, basis_e, basis_o);
    k_u<<<dim3(8, BB), 128>>>(W_K);
    k_score<<<dim3(32, BB), 256>>>(x_keys, z_query, z_keys, W_delta, log_sigma);
    k_y<<<dim3(32, BB), 256>>>(x_keys);
    k_av<<<dim3(DKK, BB), 128>>>(W_V);
    k_o<<<dim3(4, BB), 256>>>(W_O, out);
}

// round 7
// speedup vs baseline: 6.8079x; 1.2294x over previous
#include <cuda_runtime.h>
#include <math.h>
#include <stdint.h>

// Shapes (fixed by the problem)
#define BB   4
#define NN   2048
#define DD   1024
#define DLL  64
#define DKK  128
#define DCC  8

// -------- device scratch (static: no allocations allowed) --------
__device__ float g_lam[BB];
__device__ float g_q[BB*DKK];        // q / tau
__device__ float g_qB[BB*DCC*DKK];   // (q/tau)^T basis_r
__device__ float g_u[BB*9*DD];       // u_0 = W_K^T (q/tau); u_r = W_K^T qB_r
__device__ float g_score[BB*NN];
__device__ float g_screen[BB*NN];
__device__ float g_w[BB*NN];         // softmax * screen weights
__device__ float g_yp[4*BB*DD];      // partial y over 4 n-chunks
__device__ float g_av[BB*DKK];       // av = W_V y

// ======== K1: q[b,a] (scaled by 1/tau) — grid (128 a, 4 b), 128 thr ========
__global__ void __launch_bounds__(128) k_q(
    const float* __restrict__ xq, const float* __restrict__ zq,
    const float* __restrict__ WQ, const float* __restrict__ WQz,
    const float* __restrict__ WQg) {
    int a = blockIdx.x, b = blockIdx.y;
    int t = threadIdx.x;
    __shared__ float zs[DLL];
    __shared__ float red[128];
    if (t < DLL) zs[t] = zq[b*DLL + t];
    __syncthreads();
    float s = 0.f;
    const float4* wq = (const float4*)(WQ + (size_t)a*DD);
    const float4* x  = (const float4*)(xq + (size_t)b*DD);
    #pragma unroll 2
    for (int d = t; d < DD/4; d += 128) {
        float4 wv = wq[d], xv = x[d];
        s += xv.x*wv.x + xv.y*wv.y + xv.z*wv.z + xv.w*wv.w;
    }
    if (t < DLL) s += zs[t]*WQz[a*DLL + t];
    const float* G = WQg + (size_t)a*DLL*DLL;
    #pragma unroll 4
    for (int idx = t; idx < DLL*DLL; idx += 128)
        s += G[idx]*zs[idx >> 6]*zs[idx & 63];
    red[t] = s; __syncthreads();
    for (int off = 64; off > 0; off >>= 1) {
        if (t < off) red[t] += red[t+off];
        __syncthreads();
    }
    if (t == 0) {
        float rsq = 0.f;
        for (int l = 0; l < DLL; l++) rsq += zs[l]*zs[l];
        rsq = fminf(rsq, 1.f - 1e-6f);
        float lam = 2.f/(1.f - rsq + 1e-6f);
        g_q[b*DKK + a] = red[0] * lam / sqrtf((float)DKK);
        if (a == 0) g_lam[b] = lam;
    }
}

// ======== K2: qB[b,r,j] = sum_i q_i * skew-basis — grid (8 r, 4 b), 128 thr ========
__global__ void __launch_bounds__(128) k_qB(
    const float* __restrict__ bb, const float* __restrict__ be,
    const float* __restrict__ bo) {
    int r = blockIdx.x, b = blockIdx.y;
    int j = threadIdx.x;
    __shared__ float qs[DKK];
    qs[j] = g_q[b*DKK + j];
    __syncthreads();
    int rb = r << 14;
    float acc = 0.f;
    #pragma unroll 8
    for (int i = 0; i < DKK; i++) {
        int ij = rb | (i << 7) | j;
        int ji = rb | (j << 7) | i;
        float bs = (bb[ij]-bb[ji]) + 0.5f*(be[ij]-be[ji]) + 0.3f*(bo[ij]-bo[ji]);
        acc += qs[i]*bs;
    }
    g_qB[(b*DCC + r)*DKK + j] = acc;
}

// ======== K3: U[b,r,d] = sum_a e_r[a]*WK[a,d] — grid (8 dtiles, 4 b), 128 thr ========
__global__ void __launch_bounds__(128) k_u(const float* __restrict__ WK) {
    int b = blockIdx.y, t = threadIdx.x;
    int d = blockIdx.x*128 + t;
    __shared__ float e[9*DKK];
    for (int idx = t; idx < 9*DKK; idx += 128)
        e[idx] = (idx < DKK) ? g_q[b*DKK + idx] : g_qB[b*DCC*DKK + idx - DKK];
    __syncthreads();
    float acc[9];
    #pragma unroll
    for (int r = 0; r < 9; r++) acc[r] = 0.f;
    #pragma unroll 8
    for (int a = 0; a < DKK; a++) {
        float w = WK[(size_t)a*DD + d];
        #pragma unroll
        for (int r = 0; r < 9; r++) acc[r] += e[r*DKK + a]*w;
    }
    #pragma unroll
    for (int r = 0; r < 9; r++) g_u[b*9*DD + r*DD + d] = acc[r];
}

// ======== K4: scores + screening — grid (128 ntiles of 16, 4 b), 256 thr ========
__global__ void __launch_bounds__(256) k_score(
    const float* __restrict__ xk, const float* __restrict__ zq,
    const float* __restrict__ zk, const float* __restrict__ Wd,
    const float* __restrict__ logsig) {
    int b = blockIdx.y;
    int n0 = blockIdx.x * 16;
    int t = threadIdx.x, warp = t >> 5, lane = t & 31;
    __shared__ float su[9*DD];           // 36 KB
    __shared__ float scoef[16][DCC];
    __shared__ float sdist[16];
    __shared__ float szq[DLL];

    {   // stage u via float4
        const float4* src = (const float4*)(g_u + (size_t)b*9*DD);
        float4* dst = (float4*)su;
        #pragma unroll
        for (int i = 0; i < 9; i++) dst[t + i*256] = src[t + i*256];
    }
    if (t < DLL) szq[t] = zq[b*DLL + t];
    __syncthreads();

    // coeff + dist: warp handles rows 2*warp, 2*warp+1
    #pragma unroll
    for (int rr = 0; rr < 2; rr++) {
        int row = warp*2 + rr;
        int n = n0 + row;
        const float* zkp = zk + ((size_t)b*NN + n)*DLL;
        float d0 = szq[lane] - zkp[lane];
        float d1 = szq[lane+32] - zkp[lane+32];
        float dist = d0*d0 + d1*d1;
        #pragma unroll
        for (int o = 16; o; o >>= 1) dist += __shfl_xor_sync(0xffffffffu, dist, o);
        if (lane == 0) sdist[row] = dist;
        #pragma unroll
        for (int r = 0; r < DCC; r++) {
            float p = d0*Wd[r*DLL + lane] + d1*Wd[r*DLL + 32 + lane];
            #pragma unroll
            for (int o = 16; o; o >>= 1) p += __shfl_xor_sync(0xffffffffu, p, o);
            if (lane == 0) scoef[row][r] = p;
        }
    }
    __syncthreads();

    float lam = g_lam[b];
    float sfac = -expf(logsig[0]) * 0.5f * lam * lam;

    // 9-way dots for two rows per warp, float4 over d
    int row0 = warp*2;
    int n = n0 + row0;
    const float4* xp0 = (const float4*)(xk + ((size_t)b*NN + n)*DD);
    const float4* xp1 = xp0 + DD/4;
    const float4* su4 = (const float4*)su;
    float acc0[9], acc1[9];
    #pragma unroll
    for (int r = 0; r < 9; r++) { acc0[r] = 0.f; acc1[r] = 0.f; }
    #pragma unroll
    for (int k = 0; k < 8; k++) {
        float4 x0 = xp0[lane + 32*k];
        float4 x1 = xp1[lane + 32*k];
        #pragma unroll
        for (int r = 0; r < 9; r++) {
            float4 u = su4[r*256 + lane + 32*k];
            acc0[r] += x0.x*u.x + x0.y*u.y + x0.z*u.z + x0.w*u.w;
            acc1[r] += x1.x*u.x + x1.y*u.y + x1.z*u.z + x1.w*u.w;
        }
    }
    #pragma unroll
    for (int r = 0; r < 9; r++) {
        #pragma unroll
        for (int o = 16; o; o >>= 1) {
            acc0[r] += __shfl_xor_sync(0xffffffffu, acc0[r], o);
            acc1[r] += __shfl_xor_sync(0xffffffffu, acc1[r], o);
        }
    }
    if (lane == 0) {
        float s0 = acc0[0], s1 = acc1[0];
        #pragma unroll
        for (int r = 0; r < 8; r++) {
            s0 += scoef[row0][r]   * acc0[r+1];
            s1 += scoef[row0+1][r] * acc1[r+1];
        }
        g_score[b*NN + n]     = s0;
        g_score[b*NN + n + 1] = s1;
        g_screen[b*NN + n]     = expf(sfac * sdist[row0]);
        g_screen[b*NN + n + 1] = expf(sfac * sdist[row0+1]);
    }
}

// ======== K5: weights w = softmax(score) * screen — grid (4 b), 256 thr ========
__global__ void __launch_bounds__(256) k_w() {
    int b = blockIdx.x, t = threadIdx.x;
    __shared__ float red[256];
    const float* sc = g_score + b*NN;
    float m = -1e30f;
    #pragma unroll
    for (int i = t; i < NN; i += 256) m = fmaxf(m, sc[i]);
    red[t] = m; __syncthreads();
    for (int o = 128; o; o >>= 1) { if (t < o) red[t] = fmaxf(red[t], red[t+o]); __syncthreads(); }
    m = red[0]; __syncthreads();
    float z = 0.f;
    #pragma unroll
    for (int i = t; i < NN; i += 256) z += expf(sc[i] - m);
    red[t] = z; __syncthreads();
    for (int o = 128; o; o >>= 1) { if (t < o) red[t] += red[t+o]; __syncthreads(); }
    float Z = red[0];
    #pragma unroll
    for (int i = t; i < NN; i += 256)
        g_w[b*NN + i] = expf(sc[i] - m) / Z * g_screen[b*NN + i];
}

// ======== K6: partial y over n-chunks — grid (32 dtiles, 4 nchunks, 4 b), 256 thr ====
__global__ void __launch_bounds__(256) k_y(const float* __restrict__ xk) {
    int b = blockIdx.z, nc = blockIdx.y;
    int t = threadIdx.x, dl = t & 31, strip = t >> 5;
    __shared__ float sw[512];
    __shared__ float red[256];
    #pragma unroll
    for (int i = t; i < 512; i += 256) sw[i] = g_w[b*NN + nc*512 + i];
    __syncthreads();
    int d = blockIdx.x*32 + dl;
    const float* xp = xk + ((size_t)b*NN + nc*512)*DD + d;
    float acc = 0.f;
    #pragma unroll 4
    for (int n = strip; n < 512; n += 8) acc += sw[n] * xp[(size_t)n*DD];
    red[t] = acc; __syncthreads();
    if (strip == 0) {
        float s = 0.f;
        #pragma unroll
        for (int k = 0; k < 8; k++) s += red[dl + k*32];
        g_yp[(nc*BB + b)*DD + d] = s;
    }
}

// ======== K7: av[b,a] = sum_d (Σ_p yp)*WV[a,d] — grid (128 a, 4 b), 128 thr ========
__global__ void __launch_bounds__(128) k_av(const float* __restrict__ WV) {
    int a = blockIdx.x, b = blockIdx.y;
    int t = threadIdx.x;
    __shared__ float red[128];
    const float* wv = WV + (size_t)a*DD;
    float s = 0.f;
    #pragma unroll
    for (int i = 0; i < 8; i++) {
        int d = t + i*128;
        float y = g_yp[b*DD + d] + g_yp[(BB + b)*DD + d]
                + g_yp[(2*BB + b)*DD + d] + g_yp[(3*BB + b)*DD + d];
        s += y * wv[d];
    }
    red[t] = s; __syncthreads();
    for (int o = 64; o; o >>= 1) { if (t < o) red[t] += red[t+o]; __syncthreads(); }
    if (t == 0) g_av[b*DKK + a] = red[0];
}

// ======== K8: out[b,d] = sum_a av[a]*WO[d,a] — grid (4 dtiles, 4 b), 256 thr ========
__global__ void __launch_bounds__(256) k_o(const float* __restrict__ WO,
                                           float* __restrict__ out) {
    int b = blockIdx.y;
    int t = threadIdx.x;
    int d = blockIdx.x*256 + t;
    __shared__ float av[DKK];
    if (t < DKK) av[t] = g_av[b*DKK + t];
    __syncthreads();
    float s = 0.f;
    const float4* wo = (const float4*)(WO + (size_t)d*DKK);
    #pragma unroll 8
    for (int a4 = 0; a4 < 32; a4++) {
        float4 wv = wo[a4];
        s += av[a4*4+0]*wv.x + av[a4*4+1]*wv.y + av[a4*4+2]*wv.z + av[a4*4+3]*wv.w;
    }
    out[b*DD + d] = s;
}

extern "C" void kernel_launch(void* const* d_in, const int* in_sizes, int n_in,
                              void* d_out, int out_size) {
    const float* x_query   = (const float*)d_in[0];
    const float* z_query   = (const float*)d_in[1];
    const float* x_keys    = (const float*)d_in[2];
    const float* z_keys    = (const float*)d_in[3];
    const float* W_Q       = (const float*)d_in[4];
    const float* W_Qz      = (const float*)d_in[5];
    const float* W_Qg      = (const float*)d_in[6];
    const float* W_K       = (const float*)d_in[7];
    const float* W_V       = (const float*)d_in[8];
    const float* W_O       = (const float*)d_in[9];
    const float* W_delta   = (const float*)d_in[10];
    const float* basis_b   = (const float*)d_in[11];
    const float* basis_e   = (const float*)d_in[12];
    const float* basis_o   = (const float*)d_in[13];
    const float* log_sigma = (const float*)d_in[14];
    float* out = (float*)d_out;

    k_q<<<dim3(DKK, BB), 128>>>(x_query, z_query, W_Q, W_Qz, W_Qg);
    k_qB<<<dim3(DCC, BB), 128>>>(basis_b, basis_e, basis_o);
    k_u<<<dim3(8, BB), 128>>>(W_K);
    k_score<<<dim3(128, BB), 256>>>(x_keys, z_query, z_keys, W_delta, log_sigma);
    k_w<<<BB, 256>>>();
    k_y<<<dim3(32, 4, BB), 256>>>(x_keys);
    k_av<<<dim3(DKK, BB), 128>>>(W_V);
    k_o<<<dim3(4, BB), 256>>>(W_O, out);
}

// round 9
// speedup vs baseline: 9.1645x; 1.3462x over previous
#include <cuda_runtime.h>
#include <math.h>
#include <stdint.h>

// Shapes (fixed by the problem)
#define BB   4
#define NN   2048
#define DD   1024
#define DLL  64
#define DKK  128
#define DCC  8

// -------- device scratch (static: no allocations allowed) --------
__device__ float g_lam[BB];
__device__ float g_q[BB*DKK];        // q / tau
__device__ float g_qB[BB*DCC*DKK];   // (q/tau)^T basis_r
__device__ float g_u[BB*9*DD];       // u_0 = W_K^T (q/tau); u_r = W_K^T qB_r
__device__ float g_score[BB*NN];
__device__ float g_screen[BB*NN];
__device__ float g_yp[16*BB*DD];     // partial y over 16 n-chunks

// ======== K1: q[b,a] (scaled by 1/tau) — grid (128 a, 4 b), 128 thr ========
__global__ void __launch_bounds__(128) k_q(
    const float* __restrict__ xq, const float* __restrict__ zq,
    const float* __restrict__ WQ, const float* __restrict__ WQz,
    const float* __restrict__ WQg) {
    int a = blockIdx.x, b = blockIdx.y;
    int t = threadIdx.x;
    __shared__ float zs[DLL];
    __shared__ float red[128];
    if (t < DLL) zs[t] = zq[b*DLL + t];
    __syncthreads();
    float s = 0.f;
    const float4* wq = (const float4*)(WQ + (size_t)a*DD);
    const float4* x  = (const float4*)(xq + (size_t)b*DD);
    #pragma unroll 2
    for (int d = t; d < DD/4; d += 128) {
        float4 wv = wq[d], xv = x[d];
        s += xv.x*wv.x + xv.y*wv.y + xv.z*wv.z + xv.w*wv.w;
    }
    if (t < DLL) s += zs[t]*WQz[a*DLL + t];
    const float* G = WQg + (size_t)a*DLL*DLL;
    #pragma unroll 4
    for (int idx = t; idx < DLL*DLL; idx += 128)
        s += G[idx]*zs[idx >> 6]*zs[idx & 63];
    red[t] = s; __syncthreads();
    for (int off = 64; off > 0; off >>= 1) {
        if (t < off) red[t] += red[t+off];
        __syncthreads();
    }
    if (t == 0) {
        float rsq = 0.f;
        for (int l = 0; l < DLL; l++) rsq += zs[l]*zs[l];
        rsq = fminf(rsq, 1.f - 1e-6f);
        float lam = 2.f/(1.f - rsq + 1e-6f);
        g_q[b*DKK + a] = red[0] * lam / sqrtf((float)DKK);
        if (a == 0) g_lam[b] = lam;
    }
}

// ======== K2: qB for all b — grid (8 r), 256 thr, smem-transposed basis ========
__global__ void __launch_bounds__(256) k_qB(
    const float* __restrict__ bb, const float* __restrict__ be,
    const float* __restrict__ bo) {
    extern __shared__ float Gs[];        // [128][129] padded
    __shared__ float qs[BB*DKK];
    int r = blockIdx.x, t = threadIdx.x;
    for (int idx = t; idx < BB*DKK; idx += 256) qs[idx] = g_q[idx];
    size_t rb = (size_t)r << 14;
    for (int idx = t; idx < DKK*DKK; idx += 256) {
        int i = idx >> 7, j = idx & 127;
        Gs[i*129 + j] = bb[rb + idx] + 0.5f*be[rb + idx] + 0.3f*bo[rb + idx];
    }
    __syncthreads();
    int j = t & 127;
    #pragma unroll
    for (int pass = 0; pass < 2; pass++) {
        int b = (t >> 7) + pass*2;
        float acc = 0.f;
        #pragma unroll 8
        for (int i = 0; i < DKK; i++)
            acc += qs[b*DKK + i] * (Gs[i*129 + j] - Gs[j*129 + i]);
        g_qB[(b*DCC + r)*DKK + j] = acc;
    }
}

// ======== K3: U[b,r,d] = sum_a e_r[a]*WK[a,d] — grid (8 dtiles, 4 b), 128 thr ========
__global__ void __launch_bounds__(128) k_u(const float* __restrict__ WK) {
    int b = blockIdx.y, t = threadIdx.x;
    int d = blockIdx.x*128 + t;
    __shared__ float e[9*DKK];
    for (int idx = t; idx < 9*DKK; idx += 128)
        e[idx] = (idx < DKK) ? g_q[b*DKK + idx] : g_qB[b*DCC*DKK + idx - DKK];
    __syncthreads();
    float acc[9];
    #pragma unroll
    for (int r = 0; r < 9; r++) acc[r] = 0.f;
    #pragma unroll 8
    for (int a = 0; a < DKK; a++) {
        float w = WK[(size_t)a*DD + d];
        #pragma unroll
        for (int r = 0; r < 9; r++) acc[r] += e[r*DKK + a]*w;
    }
    #pragma unroll
    for (int r = 0; r < 9; r++) g_u[b*9*DD + r*DD + d] = acc[r];
}

// ======== K4: scores + screening — grid (128 ntiles of 16, 4 b), 128 thr ========
// u read straight from global (identical across warps -> L1-resident).
__global__ void __launch_bounds__(128) k_score(
    const float* __restrict__ xk, const float* __restrict__ zq,
    const float* __restrict__ zk, const float* __restrict__ Wd,
    const float* __restrict__ logsig) {
    int b = blockIdx.y;
    int n0 = blockIdx.x * 16;
    int t = threadIdx.x, warp = t >> 5, lane = t & 31;
    __shared__ float scoef[16][DCC];
    __shared__ float sdist[16];
    __shared__ float szq[DLL];
    if (t < DLL) szq[t] = zq[b*DLL + t];
    __syncthreads();

    // coeff + dist: warp handles its 4 rows
    #pragma unroll
    for (int rr = 0; rr < 4; rr++) {
        int row = warp*4 + rr;
        int n = n0 + row;
        const float* zkp = zk + ((size_t)b*NN + n)*DLL;
        float d0 = szq[lane] - zkp[lane];
        float d1 = szq[lane+32] - zkp[lane+32];
        float dist = d0*d0 + d1*d1;
        #pragma unroll
        for (int o = 16; o; o >>= 1) dist += __shfl_xor_sync(0xffffffffu, dist, o);
        if (lane == 0) sdist[row] = dist;
        #pragma unroll
        for (int r = 0; r < DCC; r++) {
            float p = d0*Wd[r*DLL + lane] + d1*Wd[r*DLL + 32 + lane];
            #pragma unroll
            for (int o = 16; o; o >>= 1) p += __shfl_xor_sync(0xffffffffu, p, o);
            if (lane == 0) scoef[row][r] = p;
        }
    }
    __syncthreads();

    float lam = g_lam[b];
    float sfac = -expf(logsig[0]) * 0.5f * lam * lam;

    // 9-way dots, 4 rows per warp, float4 over d; u via L1
    int row0 = warp*4;
    int n = n0 + row0;
    const float4* xp = (const float4*)(xk + ((size_t)b*NN + n)*DD);
    const float4* u4 = (const float4*)(g_u + (size_t)b*9*DD);
    float acc[4][9];
    #pragma unroll
    for (int i = 0; i < 4; i++)
        #pragma unroll
        for (int r = 0; r < 9; r++) acc[i][r] = 0.f;
    #pragma unroll
    for (int k = 0; k < 8; k++) {
        int dk = lane + 32*k;
        float4 uu[9];
        #pragma unroll
        for (int r = 0; r < 9; r++) uu[r] = u4[r*256 + dk];
        #pragma unroll
        for (int i = 0; i < 4; i++) {
            float4 xv = xp[(size_t)i*256 + dk];
            #pragma unroll
            for (int r = 0; r < 9; r++)
                acc[i][r] += xv.x*uu[r].x + xv.y*uu[r].y + xv.z*uu[r].z + xv.w*uu[r].w;
        }
    }
    #pragma unroll
    for (int i = 0; i < 4; i++)
        #pragma unroll
        for (int r = 0; r < 9; r++) {
            #pragma unroll
            for (int o = 16; o; o >>= 1)
                acc[i][r] += __shfl_xor_sync(0xffffffffu, acc[i][r], o);
        }
    if (lane == 0) {
        #pragma unroll
        for (int i = 0; i < 4; i++) {
            float s = acc[i][0];
            #pragma unroll
            for (int r = 0; r < 8; r++) s += scoef[row0+i][r] * acc[i][r+1];
            g_score[b*NN + n + i] = s;
            g_screen[b*NN + n + i] = expf(sfac * sdist[row0+i]);
        }
    }
}

// ======== K5: softmax stats (in-block) + partial y — grid (4 dt, 16 nc, 4 b), 256 ====
__global__ void __launch_bounds__(256) k_y(const float* __restrict__ xk) {
    int b = blockIdx.z, nc = blockIdx.y;
    int t = threadIdx.x, dl = t & 63, strip = t >> 6;
    __shared__ float red[256];
    __shared__ float sw[128];
    __shared__ float4 red4[256];
    const float* sc = g_score + b*NN;

    // softmax stats over the full row (8KB, L2-hot)
    float m = -1e30f;
    #pragma unroll
    for (int i = t; i < NN; i += 256) m = fmaxf(m, sc[i]);
    red[t] = m; __syncthreads();
    for (int o = 128; o; o >>= 1) { if (t < o) red[t] = fmaxf(red[t], red[t+o]); __syncthreads(); }
    m = red[0]; __syncthreads();
    float z = 0.f;
    #pragma unroll
    for (int i = t; i < NN; i += 256) z += expf(sc[i] - m);
    red[t] = z; __syncthreads();
    for (int o = 128; o; o >>= 1) { if (t < o) red[t] += red[t+o]; __syncthreads(); }
    float Z = red[0]; __syncthreads();

    if (t < 128) {
        int n = nc*128 + t;
        sw[t] = expf(sc[n] - m) / Z * g_screen[b*NN + n];
    }
    __syncthreads();

    int d4 = blockIdx.x*64 + dl;
    const float4* xp = (const float4*)(xk + (size_t)(b*NN + nc*128)*DD);
    float4 acc = make_float4(0.f, 0.f, 0.f, 0.f);
    #pragma unroll 8
    for (int i = 0; i < 32; i++) {
        int nn = strip*32 + i;
        float w = sw[nn];
        float4 xv = xp[(size_t)nn*256 + d4];
        acc.x += w*xv.x; acc.y += w*xv.y; acc.z += w*xv.z; acc.w += w*xv.w;
    }
    red4[t] = acc; __syncthreads();
    if (strip == 0) {
        float4 a0 = red4[dl], a1 = red4[dl+64], a2 = red4[dl+128], a3 = red4[dl+192];
        float4 s = make_float4(a0.x+a1.x+a2.x+a3.x, a0.y+a1.y+a2.y+a3.y,
                               a0.z+a1.z+a2.z+a3.z, a0.w+a1.w+a2.w+a3.w);
        *(float4*)(g_yp + (size_t)(nc*BB + b)*DD + d4*4) = s;
    }
}

// ======== K6: ysum -> av = WV y -> out = WO av — grid (4 dtiles, 4 b), 256 thr ========
__global__ void __launch_bounds__(256) k_o(const float* __restrict__ WV,
                                           const float* __restrict__ WO,
                                           float* __restrict__ out) {
    int b = blockIdx.y;
    int t = threadIdx.x, warp = t >> 5, lane = t & 31;
    __shared__ float ysum[DD];
    __shared__ float sav[DKK];
    #pragma unroll
    for (int i = t; i < DD; i += 256) {
        float s = 0.f;
        #pragma unroll
        for (int p = 0; p < 16; p++) s += g_yp[(size_t)(p*BB + b)*DD + i];
        ysum[i] = s;
    }
    __syncthreads();
    // av[a] = ysum . WV[a,:]: warp computes 16 a's
    const float4* y4 = (const float4*)ysum;
    for (int ii = 0; ii < 16; ii++) {
        int a = warp*16 + ii;
        const float4* wv = (const float4*)(WV + (size_t)a*DD);
        float s = 0.f;
        #pragma unroll
        for (int k = 0; k < 8; k++) {
            float4 w = wv[lane + 32*k];
            float4 y = y4[lane + 32*k];
            s += y.x*w.x + y.y*w.y + y.z*w.z + y.w*w.w;
        }
        #pragma unroll
        for (int o = 16; o; o >>= 1) s += __shfl_xor_sync(0xffffffffu, s, o);
        if (lane == 0) sav[a] = s;
    }
    __syncthreads();
    int d = blockIdx.x*256 + t;
    float s = 0.f;
    const float4* wo = (const float4*)(WO + (size_t)d*DKK);
    #pragma unroll 8
    for (int a4 = 0; a4 < 32; a4++) {
        float4 wv = wo[a4];
        s += sav[a4*4+0]*wv.x + sav[a4*4+1]*wv.y + sav[a4*4+2]*wv.z + sav[a4*4+3]*wv.w;
    }
    out[b*DD + d] = s;
}

extern "C" void kernel_launch(void* const* d_in, const int* in_sizes, int n_in,
                              void* d_out, int out_size) {
    const float* x_query   = (const float*)d_in[0];
    const float* z_query   = (const float*)d_in[1];
    const float* x_keys    = (const float*)d_in[2];
    const float* z_keys    = (const float*)d_in[3];
    const float* W_Q       = (const float*)d_in[4];
    const float* W_Qz      = (const float*)d_in[5];
    const float* W_Qg      = (const float*)d_in[6];
    const float* W_K       = (const float*)d_in[7];
    const float* W_V       = (const float*)d_in[8];
    const float* W_O       = (const float*)d_in[9];
    const float* W_delta   = (const float*)d_in[10];
    const float* basis_b   = (const float*)d_in[11];
    const float* basis_e   = (const float*)d_in[12];
    const float* basis_o   = (const float*)d_in[13];
    const float* log_sigma = (const float*)d_in[14];
    float* out = (float*)d_out;

    static int smem_set = 0;
    if (!smem_set) {
        cudaFuncSetAttribute(k_qB, cudaFuncAttributeMaxDynamicSharedMemorySize,
                             DKK*129*sizeof(float));
        smem_set = 1;
    }

    k_q<<<dim3(DKK, BB), 128>>>(x_query, z_query, W_Q, W_Qz, W_Qg);
    k_qB<<<DCC, 256, DKK*129*sizeof(float)>>>(basis_b, basis_e, basis_o);
    k_u<<<dim3(8, BB), 128>>>(W_K);
    k_score<<<dim3(128, BB), 128>>>(x_keys, z_query, z_keys, W_delta, log_sigma);
    k_y<<<dim3(4, 16, BB), 256>>>(x_keys);
    k_o<<<dim3(4, BB), 256>>>(W_V, W_O, out);
}